// round 1
// baseline (speedup 1.0000x reference)
#include <cuda_runtime.h>

#define SEQ    4096
#define HID    512
#define G4     2048          // 4*HID
#define NCD    64            // CTAs per direction in the recurrence
#define ROWSL  32            // gate rows per CTA (4 gates * JH)
#define JH     8             // h outputs per CTA

// ---------------- scratch (device globals; no allocation allowed) ----------------
static __device__ __align__(16) float    g_x0 [SEQ * HID];        // embedded input
static __device__ __align__(16) float    g_xpf[SEQ * G4];         // xproj forward (reused per layer)
static __device__ __align__(16) float    g_xpb[SEQ * G4];         // xproj backward
static __device__ __align__(16) float    g_h0 [SEQ * 2 * HID];    // layer0 output (concat f,b)
static __device__ __align__(16) float    g_h1 [SEQ * 2 * HID];    // layer1 output
static __device__ __align__(16) float    g_hbuf[2][2 * HID];      // [dir][parity*HID] hidden state
static __device__                unsigned g_bar[2];               // per-direction step counters

// ---------------- embed ----------------
__global__ void embed_kernel(const int* __restrict__ idx, const float* __restrict__ ew) {
    int s = blockIdx.x;               // 4096 blocks, 128 threads
    int r = idx[s];
    ((float4*)(g_x0 + (size_t)s * HID))[threadIdx.x] =
        ((const float4*)(ew + (size_t)r * HID))[threadIdx.x];
}

__global__ void reset_kernel() {
    if (threadIdx.x < 2) g_bar[threadIdx.x] = 0u;
}

// ---------------- fp32 GEMM:  C[M][N] = A[M][K] * B[N][K]^T + bias[N] ----------------
// Tiles: BM=128, BN=256, BK=8; 256 threads; 8x16 microtile; packed f32x2 FMA.
__device__ __forceinline__ unsigned long long dupf(float a) {
    unsigned long long r;
    unsigned ai = __float_as_uint(a);
    asm("mov.b64 %0, {%1, %2};" : "=l"(r) : "r"(ai), "r"(ai));
    return r;
}
#define FFMA2(acc_, a_, b_) asm("fma.rn.f32x2 %0, %1, %2, %0;" : "+l"(acc_) : "l"(a_), "l"(b_))

__global__ void __launch_bounds__(256, 1) gemm_nt_bias(
    const float* __restrict__ A,     // [M][K]
    const float* __restrict__ B,     // [N][K]
    const float* __restrict__ bias,  // [N]
    float* __restrict__ C,           // [M][N]
    int M, int N, int K)
{
    __shared__ __align__(16) float As[2][8][128];
    __shared__ __align__(16) float Bs[2][8][256];

    const int tid = threadIdx.x;
    const int bm  = blockIdx.y * 128;
    const int bn  = blockIdx.x * 256;
    const int tx  = tid & 15;         // 16 col-groups of 16
    const int ty  = tid >> 4;         // 16 row-groups of 8

    // global load assignments
    const int arow = tid >> 1;                 // 0..127
    const int akc  = (tid & 1) * 4;            // 0 or 4
    const float* Ap = A + (size_t)(bm + arow) * K + akc;
    const float* Bp = B + (size_t)(bn + tid) * K;

    float4 aR  = __ldg((const float4*)Ap);
    float4 bR0 = __ldg((const float4*)Bp);
    float4 bR1 = __ldg((const float4*)(Bp + 4));

    unsigned long long acc[8][8];
#pragma unroll
    for (int i = 0; i < 8; i++)
#pragma unroll
        for (int j = 0; j < 8; j++) acc[i][j] = 0ull;

    const int nk = K >> 3;
    for (int kt = 0; kt < nk; kt++) {
        const int buf = kt & 1;
        // stage tile into SMEM (A transposed to [k][row], B to [k][col])
        As[buf][akc + 0][arow] = aR.x;
        As[buf][akc + 1][arow] = aR.y;
        As[buf][akc + 2][arow] = aR.z;
        As[buf][akc + 3][arow] = aR.w;
        Bs[buf][0][tid] = bR0.x;  Bs[buf][1][tid] = bR0.y;
        Bs[buf][2][tid] = bR0.z;  Bs[buf][3][tid] = bR0.w;
        Bs[buf][4][tid] = bR1.x;  Bs[buf][5][tid] = bR1.y;
        Bs[buf][6][tid] = bR1.z;  Bs[buf][7][tid] = bR1.w;
        __syncthreads();
        if (kt + 1 < nk) {
            aR  = __ldg((const float4*)(Ap + (size_t)(kt + 1) * 8));
            bR0 = __ldg((const float4*)(Bp + (size_t)(kt + 1) * 8));
            bR1 = __ldg((const float4*)(Bp + (size_t)(kt + 1) * 8 + 4));
        }
#pragma unroll
        for (int k = 0; k < 8; k++) {
            const float* ak = &As[buf][k][ty * 8];
            float4 a0 = *(const float4*)ak;
            float4 a1 = *(const float4*)(ak + 4);
            const double2* bk = (const double2*)&Bs[buf][k][tx * 16];
            double2 q0 = bk[0], q1 = bk[1], q2 = bk[2], q3 = bk[3];
            unsigned long long bb[8];
            bb[0] = __double_as_longlong(q0.x);  bb[1] = __double_as_longlong(q0.y);
            bb[2] = __double_as_longlong(q1.x);  bb[3] = __double_as_longlong(q1.y);
            bb[4] = __double_as_longlong(q2.x);  bb[5] = __double_as_longlong(q2.y);
            bb[6] = __double_as_longlong(q3.x);  bb[7] = __double_as_longlong(q3.y);
            float av[8] = {a0.x, a0.y, a0.z, a0.w, a1.x, a1.y, a1.z, a1.w};
#pragma unroll
            for (int i = 0; i < 8; i++) {
                unsigned long long ad = dupf(av[i]);
#pragma unroll
                for (int j = 0; j < 8; j++) FFMA2(acc[i][j], ad, bb[j]);
            }
        }
        // single sync per iteration is sufficient (see double-buffer ordering proof)
    }

    // epilogue: bias + store
    float bias16[16];
#pragma unroll
    for (int q = 0; q < 4; q++)
        *(float4*)&bias16[q * 4] = __ldg((const float4*)&bias[bn + tx * 16 + q * 4]);
#pragma unroll
    for (int i = 0; i < 8; i++) {
        float outv[16];
#pragma unroll
        for (int j = 0; j < 8; j++) {
            union { unsigned long long u; float2 f; } cv;
            cv.u = acc[i][j];
            outv[2 * j]     = cv.f.x + bias16[2 * j];
            outv[2 * j + 1] = cv.f.y + bias16[2 * j + 1];
        }
        float* crow = C + (size_t)(bm + ty * 8 + i) * N + bn + tx * 16;
#pragma unroll
        for (int q = 0; q < 4; q++) *(float4*)&crow[q * 4] = *(float4*)&outv[q * 4];
    }
}

// ---------------- persistent bidirectional LSTM layer ----------------
// grid = 2*NCD CTAs (dir = blockIdx.x>>6), 256 threads, dynamic SMEM.
// Each CTA owns JH=8 h-outputs => 32 gate rows of Whh resident in SMEM (fp32).
// Steps synchronized with an atomic-counter barrier per direction.
__global__ void __launch_bounds__(256, 1) lstm_layer_kernel(
    const float* __restrict__ xpf, const float* __restrict__ xpb,
    const float* __restrict__ Whf, const float* __restrict__ Whb,
    float* __restrict__ hcat)
{
    extern __shared__ float sm[];
    float* Wsh = sm;                       // ROWSL*HID
    float* hsh = sm + ROWSL * HID;         // HID
    float* xps = hsh + HID;                // 32
    float* pre = xps + 32;                 // 32
    float* csh = pre + 32;                 // JH

    const int tid = threadIdx.x;
    const int dir = blockIdx.x >> 6;       // NCD == 64
    const int cid = blockIdx.x & 63;
    const float* xp = dir ? xpb : xpf;
    const float* W  = dir ? Whb : Whf;
    unsigned* bar = &g_bar[dir];
    float* hbuf = g_hbuf[dir];

    // load this CTA's Whh slice: local row rl = g*8 + j  <->  global row g*512 + cid*8 + j
    for (int rl = 0; rl < ROWSL; rl++) {
        int g = rl >> 3, j = rl & 7;
        size_t grow = (size_t)(g * HID + cid * JH + j) * HID;
        int k = tid * 4;
        if (k < HID)
            *(float4*)&Wsh[rl * HID + k] = __ldg((const float4*)&W[grow + k]);
    }
    if (tid < 128) ((float4*)hsh)[tid] = make_float4(0.f, 0.f, 0.f, 0.f);
    if (tid < JH) csh[tid] = 0.f;
    __syncthreads();

    const int rp   = tid >> 4;             // 16 row-pairs
    const int ks   = tid & 15;             // 16 k-slices (strided by 4 floats)
    const int row0 = rp * 2, row1 = rp * 2 + 1;
    const float* w0 = &Wsh[row0 * HID];
    const float* w1 = &Wsh[row1 * HID];

    for (int t = 0; t < SEQ; t++) {
        const int tt = dir ? (SEQ - 1 - t) : t;
        if (t > 0) {
            if (tid == 0) {
                const unsigned target = (unsigned)NCD * (unsigned)t;
                while (atomicAdd(bar, 0u) < target) { }
                __threadfence();           // acquire
            }
            __syncthreads();
            if (tid < 128) {
                const float4* hp = (const float4*)&hbuf[((t - 1) & 1) * HID];
                ((float4*)hsh)[tid] = __ldcg(hp + tid);   // L2 (bypass stale L1)
            }
            __syncthreads();
        }
        // prefetch this step's xproj values (already include bias)
        float xval = 0.f;
        if (tid < 32) {
            int g = tid >> 3, j = tid & 7;
            xval = __ldg(&xp[(size_t)tt * G4 + g * HID + cid * JH + j]);
        }
        // matvec: pre[r] = sum_k h[k] * Whh[r][k], 2 rows per thread, strided k
        float a0 = 0.f, a1 = 0.f;
#pragma unroll
        for (int m = 0; m < 8; m++) {
            int k = ks * 4 + m * 64;
            float4 h4 = *(const float4*)&hsh[k];
            float4 wa = *(const float4*)&w0[k];
            float4 wb = *(const float4*)&w1[k];
            a0 += h4.x * wa.x + h4.y * wa.y + h4.z * wa.z + h4.w * wa.w;
            a1 += h4.x * wb.x + h4.y * wb.y + h4.z * wb.z + h4.w * wb.w;
        }
#pragma unroll
        for (int off = 8; off > 0; off >>= 1) {
            a0 += __shfl_down_sync(0xffffffffu, a0, off, 16);
            a1 += __shfl_down_sync(0xffffffffu, a1, off, 16);
        }
        if (ks == 0) { pre[row0] = a0; pre[row1] = a1; }
        if (tid < 32) xps[tid] = xval;
        __syncthreads();

        if (tid < JH) {
            const int j = tid;
            float zi = xps[j]      + pre[j];
            float zf = xps[8 + j]  + pre[8 + j];
            float zg = xps[16 + j] + pre[16 + j];
            float zo = xps[24 + j] + pre[24 + j];
            float ig = 1.f / (1.f + expf(-zi));
            float fg = 1.f / (1.f + expf(-zf));
            float gg = tanhf(zg);
            float og = 1.f / (1.f + expf(-zo));
            float c  = fg * csh[j] + ig * gg;
            csh[j] = c;
            float h = og * tanhf(c);
            const int hj = cid * JH + j;
            __stcg(&hbuf[(t & 1) * HID + hj], h);                     // broadcast state
            hcat[(size_t)tt * (2 * HID) + dir * HID + hj] = h;        // layer output
            __threadfence();                                          // release stores
        }
        __syncthreads();
        if (tid == 0) atomicAdd(bar, 1u);
    }
}

// ---------------- launch ----------------
extern "C" void kernel_launch(void* const* d_in, const int* in_sizes, int n_in,
                              void* d_out, int out_size)
{
    (void)in_sizes; (void)n_in; (void)out_size;
    const int*   idx   = (const int*)  d_in[0];
    const float* ew    = (const float*)d_in[1];
    const float* Wih0f = (const float*)d_in[2];
    const float* Whh0f = (const float*)d_in[3];
    const float* b0f   = (const float*)d_in[4];
    const float* Wih0b = (const float*)d_in[5];
    const float* Whh0b = (const float*)d_in[6];
    const float* b0b   = (const float*)d_in[7];
    const float* Wih1f = (const float*)d_in[8];
    const float* Whh1f = (const float*)d_in[9];
    const float* b1f   = (const float*)d_in[10];
    const float* Wih1b = (const float*)d_in[11];
    const float* Whh1b = (const float*)d_in[12];
    const float* b1b   = (const float*)d_in[13];
    const float* Wlin  = (const float*)d_in[14];
    const float* blin  = (const float*)d_in[15];
    float* out = (float*)d_out;

    float *x0, *xpf, *xpb, *h0, *h1;
    cudaGetSymbolAddress((void**)&x0,  g_x0);
    cudaGetSymbolAddress((void**)&xpf, g_xpf);
    cudaGetSymbolAddress((void**)&xpb, g_xpb);
    cudaGetSymbolAddress((void**)&h0,  g_h0);
    cudaGetSymbolAddress((void**)&h1,  g_h1);

    const int lstm_smem = (ROWSL * HID + HID + 32 + 32 + JH) * (int)sizeof(float);
    cudaFuncSetAttribute(lstm_layer_kernel, cudaFuncAttributeMaxDynamicSharedMemorySize, lstm_smem);

    // 1) embed
    embed_kernel<<<SEQ, 128>>>(idx, ew);

    // 2) layer-0 input projections (K=512, N=2048)
    {
        dim3 grid(G4 / 256, SEQ / 128);
        gemm_nt_bias<<<grid, 256>>>(x0, Wih0f, b0f, xpf, SEQ, G4, HID);
        gemm_nt_bias<<<grid, 256>>>(x0, Wih0b, b0b, xpb, SEQ, G4, HID);
    }
    // 3) layer-0 recurrence
    reset_kernel<<<1, 32>>>();
    lstm_layer_kernel<<<2 * NCD, 256, lstm_smem>>>(xpf, xpb, Whh0f, Whh0b, h0);

    // 4) layer-1 input projections (K=1024, N=2048) — reuse xp buffers
    {
        dim3 grid(G4 / 256, SEQ / 128);
        gemm_nt_bias<<<grid, 256>>>(h0, Wih1f, b1f, xpf, SEQ, G4, 2 * HID);
        gemm_nt_bias<<<grid, 256>>>(h0, Wih1b, b1b, xpb, SEQ, G4, 2 * HID);
    }
    // 5) layer-1 recurrence
    reset_kernel<<<1, 32>>>();
    lstm_layer_kernel<<<2 * NCD, 256, lstm_smem>>>(xpf, xpb, Whh1f, Whh1b, h1);

    // 6) output head: [4096,1024] x [32000,1024]^T + blin
    {
        dim3 grid(32000 / 256, SEQ / 128);
        gemm_nt_bias<<<grid, 256>>>(h1, Wlin, blin, out, SEQ, 32000, 2 * HID);
    }
}